// round 13
// baseline (speedup 1.0000x reference)
#include <cuda_runtime.h>
#include <math.h>

#define DD 512
#define AA 256
#define BB 256
#define DSPLIT 16                            // grid.z (R9: 8 -> 16; 8192 CTAs = 6.92 waves, 92%-full tail)
#define ROWS_PER_BLOCK (DD / DSPLIT)         // 32
#define ROWS_PER_THREAD (ROWS_PER_BLOCK / 4) // 8

// DEPTHS = linspace(0,50,512) -> h = 50/511; ANGLES = linspace(-30,30,256).
// P = exp(-2*diff^2) masked by 0 < d/cos < 50, normalized over depth.
//
// Poisson summation: sum_{n in Z} exp(-(nH-t)^2/(2 s^2)) = (s*sqrt(2pi)/H) *
// (1 + 2 exp(-2 pi^2 s^2 / H^2) cos(...)). With s=0.5, H=50/511 the correction
// is exp(-515) == 0, so whenever [t-5, t+5] lies inside [0, 50] the discrete
// column sum equals the EXACT constant C = s*sqrt(2pi)/H. Only columns with
// t<5 or t>45 (clipped support) need the explicit windowed sum.

__device__ __forceinline__ float ex2_ftz(float x) {
    float r;
    asm("ex2.approx.ftz.f32 %0, %1;" : "=f"(r) : "f"(x));
    return r;
}

__global__ void __launch_bounds__(256, 8)
prior_kernel(const float* __restrict__ p,
             const float* __restrict__ pc,
             float* __restrict__ out)
{
    __shared__ float s_t[AA];
    __shared__ float s_inv[AA];

    const int b     = blockIdx.x;
    const int which = blockIdx.y;
    const int tid   = threadIdx.x;

    const float DEG2RAD  = 0.017453292519943295f;
    const float ANG_STEP = 60.0f / 255.0f;
    const float H        = 50.0f / 511.0f;
    const float INV_H    = 511.0f / 50.0f;
    const float C2       = -2.8853900817779268f;             // -2/ln2
    // 1/C = H / (sigma*sqrt(2*pi)), folded at compile time in double
    const float INV_C    = (float)((50.0 / 511.0) / (0.5 * 2.5066282746310002));

    // ---- Phase 1: per-column t and 1/colsum (thread tid <-> angle tid) ----
    {
        const float* src = which ? pc : p;
        const float d_val   = src[b * 3 + 1];
        const float theta_p = src[b * 3 + 2];

        const float angle = (theta_p + (-30.0f + (float)tid * ANG_STEP)) * DEG2RAD;
        const float t = d_val / cosf(angle);   // accurate cosf: error amplifies
                                               // through the Gaussian slope
        float inv = 0.0f;
        if (t > 0.0f && t < 50.0f) {
            if (t >= 5.0f && t <= 45.0f) {
                inv = INV_C;                   // unclipped: exact constant sum
            } else {
                // clipped column: explicit windowed sum (tail beyond |z|=5
                // contributes < 1e-21)
                int lo = max((int)ceilf((t - 5.0f) * INV_H), 0);
                int hi = min((int)floorf((t + 5.0f) * INV_H), DD - 1);
                float sum = 0.0f;
                for (int di = lo; di <= hi; ++di) {
                    float z = (float)di * H - t;
                    sum += ex2_ftz(C2 * z * z);
                }
                inv = (sum > 0.0f) ? (1.0f / sum) : 1.0f;
            }
        }
        s_t[tid]   = t;
        s_inv[tid] = inv;
    }
    __syncthreads();

    // ---- Phase 2: stream stores. Thread owns 4 angles x 8 depth rows. ----
    const int aq   = tid & 63;          // angle quad: angles 4*aq .. 4*aq+3
    const int dsub = tid >> 6;          // 0..3
    const int d0   = blockIdx.z * ROWS_PER_BLOCK + dsub * ROWS_PER_THREAD;
    const int a0   = aq * 4;

    const float t0 = s_t[a0 + 0], t1 = s_t[a0 + 1], t2 = s_t[a0 + 2], t3 = s_t[a0 + 3];
    const float i0 = s_inv[a0 + 0], i1 = s_inv[a0 + 1], i2 = s_inv[a0 + 2], i3 = s_inv[a0 + 3];

    float z0 = (float)d0 * H - t0;
    float z1 = (float)d0 * H - t1;
    float z2 = (float)d0 * H - t2;
    float z3 = (float)d0 * H - t3;

    float4* outp = (float4*)(out
        + (((size_t)which * BB + b) * DD + d0) * (size_t)AA + a0);
    const int row_stride = AA / 4;

    #pragma unroll
    for (int r = 0; r < ROWS_PER_THREAD; ++r) {
        float4 v;
        v.x = ex2_ftz(C2 * z0 * z0) * i0;   // ftz underflow -> exact 0 outside
        v.y = ex2_ftz(C2 * z1 * z1) * i1;   // the support, no predicate needed
        v.z = ex2_ftz(C2 * z2 * z2) * i2;
        v.w = ex2_ftz(C2 * z3 * z3) * i3;
        __stcs(outp + (size_t)r * row_stride, v);   // streaming, evict-first
        z0 += H; z1 += H; z2 += H; z3 += H;
    }
}

extern "C" void kernel_launch(void* const* d_in, const int* in_sizes, int n_in,
                              void* d_out, int out_size)
{
    const float* p  = (const float*)d_in[0];
    const float* pc = (const float*)d_in[1];
    float* out = (float*)d_out;

    prior_kernel<<<dim3(BB, 2, DSPLIT), 256>>>(p, pc, out);
}

// round 14
// speedup vs baseline: 1.3629x; 1.3629x over previous
#include <cuda_runtime.h>
#include <math.h>

#define DD 512
#define AA 256
#define BB 256
#define DSPLIT 16                            // 8192 CTAs = 6.92 waves, 92%-full tail
#define ROWS_PER_BLOCK (DD / DSPLIT)         // 32
#define ROWS_PER_THREAD (ROWS_PER_BLOCK / 4) // 8

// DEPTHS = linspace(0,50,512) -> H = 50/511; ANGLES = linspace(-30,30,256).
// P = exp(-2*diff^2) masked by 0 < d/cos < 50, normalized over depth.
//
// Unclipped columns (5 <= t <= 45): Poisson summation makes the discrete
// column sum the EXACT constant C = sigma*sqrt(2pi)/H (correction e^-515).
// Clipped columns: Euler-Maclaurin closed form
//   S = (C/2)(erf(u_hi)-erf(u_lo)) + (f(lo)+f(hi))/2 + (f'(hi)-f'(lo))/12
// next term < 1e-5 absolute vs S >= 6.4  -> rel err ~1e-6. No loop, no
// divergence: phase-1 is uniform ~25 ops, so DSPLIT=16 duplication is cheap.

__device__ __forceinline__ float ex2_ftz(float x) {
    float r;
    asm("ex2.approx.ftz.f32 %0, %1;" : "=f"(r) : "f"(x));
    return r;
}

__global__ void __launch_bounds__(256, 8)
prior_kernel(const float* __restrict__ p,
             const float* __restrict__ pc,
             float* __restrict__ out)
{
    __shared__ float s_t[AA];
    __shared__ float s_inv[AA];

    const int b     = blockIdx.x;
    const int which = blockIdx.y;
    const int tid   = threadIdx.x;

    const float DEG2RAD  = 0.017453292519943295f;
    const float ANG_STEP = 60.0f / 255.0f;
    const float H        = 50.0f / 511.0f;
    const float INV_H    = 511.0f / 50.0f;
    const float C2       = -2.8853900817779268f;             // -2/ln2
    const float SQRT2    = 1.4142135623730951f;
    // C = sigma*sqrt(2pi)/H, folded in double at compile time
    const float CSUM     = (float)(0.5 * 2.5066282746310002 * 511.0 / 50.0);
    const float INV_C    = (float)((50.0 / 511.0) / (0.5 * 2.5066282746310002));

    // ---- Phase 1: per-column t and 1/colsum (thread tid <-> angle tid) ----
    {
        const float* src = which ? pc : p;
        const float d_val   = src[b * 3 + 1];
        const float theta_p = src[b * 3 + 2];

        const float angle = (theta_p + (-30.0f + (float)tid * ANG_STEP)) * DEG2RAD;
        const float t = d_val / cosf(angle);   // accurate cosf: error amplifies
                                               // through the Gaussian slope
        float inv = 0.0f;
        if (t > 0.0f && t < 50.0f) {
            if (t >= 5.0f && t <= 45.0f) {
                inv = INV_C;                   // unclipped: exact constant sum
            } else {
                // clipped: Euler-Maclaurin closed form over [lo, hi]
                int lo = max((int)ceilf((t - 5.0f) * INV_H), 0);
                int hi = min((int)floorf((t + 5.0f) * INV_H), DD - 1);
                float zl = (float)lo * H - t;          // nH - t at endpoints
                float zh = (float)hi * H - t;
                float fl = ex2_ftz(C2 * zl * zl);      // f = exp(-2 z^2)
                float fh = ex2_ftz(C2 * zh * zh);
                // integral term: (C/2) * (erf(zh*sqrt2) - erf(zl*sqrt2))
                float S = 0.5f * CSUM * (erff(zh * SQRT2) - erff(zl * SQRT2));
                // + trapezoid boundary + first derivative correction
                // f'(n) = -4*H*z*f
                S += 0.5f * (fl + fh);
                S += (-4.0f * H / 12.0f) * (zh * fh - zl * fl);
                inv = (S > 0.0f) ? (1.0f / S) : 1.0f;
            }
        }
        s_t[tid]   = t;
        s_inv[tid] = inv;
    }
    __syncthreads();

    // ---- Phase 2: stream stores. Thread owns 4 angles x 8 depth rows. ----
    const int aq   = tid & 63;          // angle quad: angles 4*aq .. 4*aq+3
    const int dsub = tid >> 6;          // 0..3
    const int d0   = blockIdx.z * ROWS_PER_BLOCK + dsub * ROWS_PER_THREAD;
    const int a0   = aq * 4;

    const float t0 = s_t[a0 + 0], t1 = s_t[a0 + 1], t2 = s_t[a0 + 2], t3 = s_t[a0 + 3];
    const float i0 = s_inv[a0 + 0], i1 = s_inv[a0 + 1], i2 = s_inv[a0 + 2], i3 = s_inv[a0 + 3];

    float z0 = (float)d0 * H - t0;
    float z1 = (float)d0 * H - t1;
    float z2 = (float)d0 * H - t2;
    float z3 = (float)d0 * H - t3;

    float4* outp = (float4*)(out
        + (((size_t)which * BB + b) * DD + d0) * (size_t)AA + a0);
    const int row_stride = AA / 4;

    #pragma unroll
    for (int r = 0; r < ROWS_PER_THREAD; ++r) {
        float4 v;
        v.x = ex2_ftz(C2 * z0 * z0) * i0;   // ftz underflow -> exact 0 outside
        v.y = ex2_ftz(C2 * z1 * z1) * i1;   // the support, no predicate needed
        v.z = ex2_ftz(C2 * z2 * z2) * i2;
        v.w = ex2_ftz(C2 * z3 * z3) * i3;
        __stcs(outp + (size_t)r * row_stride, v);   // streaming, evict-first
        z0 += H; z1 += H; z2 += H; z3 += H;
    }
}

extern "C" void kernel_launch(void* const* d_in, const int* in_sizes, int n_in,
                              void* d_out, int out_size)
{
    const float* p  = (const float*)d_in[0];
    const float* pc = (const float*)d_in[1];
    float* out = (float*)d_out;

    prior_kernel<<<dim3(BB, 2, DSPLIT), 256>>>(p, pc, out);
}